// round 8
// baseline (speedup 1.0000x reference)
#include <cuda_runtime.h>

#define H     51
#define G     204
#define BB    8
#define TPB   384
#define NCTA  128
#define T_IN  512
#define T_FUT 64
#define T_TOT 576
#define NTICK 514

typedef unsigned long long ull;

struct __align__(16) Smem {
    float2 W1[H + 1][102];   // k=0: W_ih1; k=1..51: W_hh1 col k-1; pair (ga,gb)
    float2 W2[2 * H][102];   // k=0..50: W_ih2 col k; 51..101: W_hh2 col k-51
    float2 W3[2 * H][102];
    float2 bp[3][102];       // bias pairs
    float  wlin[52];
    float  blin;
    float  padA[3];
    float  hcat[2][154][BB]; // ping-pong: row 0 = x; 1..51 h1; 52..102 h2; 103..153 h3
    float  c[3 * H][BB];     // c-state parking for the future phase
};

__device__ __forceinline__ ull pack2(float x) {
    ull r; asm("mov.b64 %0, {%1, %1};" : "=l"(r) : "f"(x)); return r;
}
__device__ __forceinline__ void unpack2(ull v, float &a, float &b) {
    asm("mov.b64 {%0, %1}, %2;" : "=f"(a), "=f"(b) : "l"(v));
}
__device__ __forceinline__ ull fma2(ull a, ull b, ull c) {
    ull d; asm("fma.rn.f32x2 %0, %1, %2, %3;" : "=l"(d) : "l"(a), "l"(b), "l"(c)); return d;
}
__device__ __forceinline__ ull add2(ull a, ull b) {
    ull d; asm("add.rn.f32x2 %0, %1, %2;" : "=l"(d) : "l"(a), "l"(b)); return d;
}
__device__ __forceinline__ float sigf(float x) {
    return __fdividef(1.0f, 1.0f + __expf(-x));
}
__device__ __forceinline__ float tanh_(float x) {
    return 1.0f - __fdividef(2.0f, __expf(2.0f * x) + 1.0f);
}

__device__ __forceinline__ void mac8(ull acc[8], float2 w, const float *row) {
    ulonglong2 va = *(const ulonglong2 *)row;
    ulonglong2 vb = *(const ulonglong2 *)(row + 4);
    ull wx = pack2(w.x), wy = pack2(w.y);
    acc[0] = fma2(wx, va.x, acc[0]); acc[1] = fma2(wx, va.y, acc[1]);
    acc[2] = fma2(wx, vb.x, acc[2]); acc[3] = fma2(wx, vb.y, acc[3]);
    acc[4] = fma2(wy, va.x, acc[4]); acc[5] = fma2(wy, va.y, acc[5]);
    acc[6] = fma2(wy, vb.x, acc[6]); acc[7] = fma2(wy, vb.y, acc[7]);
}

__device__ __forceinline__ void gates(const float2 (*__restrict__ W)[102],
                                      float2 bv, const float (*__restrict__ V)[BB],
                                      int K, int lc, ull acc[8]) {
    ull bx = pack2(bv.x), by = pack2(bv.y);
#pragma unroll
    for (int i = 0; i < 4; i++) { acc[i] = bx; acc[4 + i] = by; }
#pragma unroll 2
    for (int k = 0; k < K; k++) mac8(acc, W[k][lc], &V[k][0]);
}

// cell update for 4 batch elems; sel picks which packed halves are local
__device__ __forceinline__ void cell4(const ull acc[8], const ull prt[8], int sel,
                                      float creg[4], float hn[4]) {
    ull iv0, iv1, gv0, gv1, fv0, fv1, ov0, ov1;
    if (sel == 0) {
        iv0 = acc[0]; iv1 = acc[1]; gv0 = acc[4]; gv1 = acc[5];
        fv0 = prt[0]; fv1 = prt[1]; ov0 = prt[4]; ov1 = prt[5];
    } else {
        iv0 = prt[2]; iv1 = prt[3]; gv0 = prt[6]; gv1 = prt[7];
        fv0 = acc[2]; fv1 = acc[3]; ov0 = acc[6]; ov1 = acc[7];
    }
    float ig[4], fg[4], gg[4], og[4];
    unpack2(iv0, ig[0], ig[1]); unpack2(iv1, ig[2], ig[3]);
    unpack2(fv0, fg[0], fg[1]); unpack2(fv1, fg[2], fg[3]);
    unpack2(gv0, gg[0], gg[1]); unpack2(gv1, gg[2], gg[3]);
    unpack2(ov0, og[0], og[1]); unpack2(ov1, og[2], og[3]);
#pragma unroll
    for (int u = 0; u < 4; u++) {
        float cn = sigf(fg[u]) * creg[u] + sigf(ig[u]) * tanh_(gg[u]);
        hn[u]    = sigf(og[u]) * tanh_(cn);
        creg[u]  = cn;
    }
}

__device__ __forceinline__ float head_dot(const Smem *s, const float (*hb)[BB], int b) {
    float sum = s->blin;
#pragma unroll 3
    for (int j = 0; j < H; j++) sum = fmaf(s->wlin[j], hb[103 + j][b], sum);
    return sum;
}

__global__ void __launch_bounds__(TPB, 1)
lstm_seq_kernel(const float *__restrict__ input,
                const float *__restrict__ W_ih1, const float *__restrict__ W_hh1,
                const float *__restrict__ b_ih1, const float *__restrict__ b_hh1,
                const float *__restrict__ W_ih2, const float *__restrict__ W_hh2,
                const float *__restrict__ b_ih2, const float *__restrict__ b_hh2,
                const float *__restrict__ W_ih3, const float *__restrict__ W_hh3,
                const float *__restrict__ b_ih3, const float *__restrict__ b_hh3,
                const float *__restrict__ W_lin, const float *__restrict__ b_lin,
                float *__restrict__ out) {
    extern __shared__ char raw[];
    Smem *s = (Smem *)raw;

    const int tid = threadIdx.x;
    const int b0  = blockIdx.x * BB;
    const int L   = tid >> 7;       // layer block: warps 0-3 / 4-7 / 8-11
    const int l   = tid & 127;
    const int lc  = (l < 102) ? l : 101;
    const int j   = lc >> 1;
    const int sel = lc & 1;
    const bool gate_lane = (l < 102);
    const bool head_lane = (L == 0) && (l >= 102) && (l < 102 + BB);
    const bool xf_lane   = (L == 1) && (l >= 102) && (l < 102 + BB);

    // ---- one-time staging (pair (ga,gb) = (j+sel*51, j+sel*51+102)) ----
    for (int idx = tid; idx < (H + 1) * 102; idx += TPB) {
        int k = idx / 102, l2 = idx % 102;
        int ga = (l2 >> 1) + (l2 & 1) * 51, gb = ga + 102;
        float2 v;
        if (k == 0) v = make_float2(W_ih1[ga], W_ih1[gb]);
        else        v = make_float2(W_hh1[ga * H + k - 1], W_hh1[gb * H + k - 1]);
        s->W1[k][l2] = v;
    }
    for (int idx = tid; idx < 2 * H * 102; idx += TPB) {
        int k = idx / 102, l2 = idx % 102;
        int ga = (l2 >> 1) + (l2 & 1) * 51, gb = ga + 102;
        int kk = (k < H) ? k : k - H;
        const float *s2 = (k < H) ? W_ih2 : W_hh2;
        const float *s3 = (k < H) ? W_ih3 : W_hh3;
        s->W2[k][l2] = make_float2(s2[ga * H + kk], s2[gb * H + kk]);
        s->W3[k][l2] = make_float2(s3[ga * H + kk], s3[gb * H + kk]);
    }
    for (int idx = tid; idx < 3 * 102; idx += TPB) {
        int ly = idx / 102, l2 = idx % 102;
        int ga = (l2 >> 1) + (l2 & 1) * 51, gb = ga + 102;
        const float *bi = (ly == 0) ? b_ih1 : (ly == 1) ? b_ih2 : b_ih3;
        const float *bh = (ly == 0) ? b_hh1 : (ly == 1) ? b_hh2 : b_hh3;
        s->bp[ly][l2] = make_float2(bi[ga] + bh[ga], bi[gb] + bh[gb]);
    }
    if (tid < H) s->wlin[tid] = W_lin[tid];
    if (tid == 0) s->blin = b_lin[0];
    for (int idx = tid; idx < 2 * 154 * BB; idx += TPB) (&s->hcat[0][0][0])[idx] = 0.0f;
    __syncthreads();
    if (tid < BB) s->hcat[0][0][tid] = input[(size_t)(b0 + tid) * T_IN];  // x(0)
    __syncthreads();

    float creg[4] = {0.f, 0.f, 0.f, 0.f};

    // ===== pipelined main loop: ONE barrier per tick (ping-pong hcat) =====
    for (int t = 0; t < NTICK; t++) {
        const float (*hr)[BB] = s->hcat[t & 1];
        float (*hw)[BB]       = s->hcat[(t + 1) & 1];
        ull   acc[8] = {};
        float xr = 0.0f;
        if (gate_lane) {
            if (L == 0)      gates(s->W1, s->bp[0][lc], hr,      H + 1, lc, acc);
            else if (L == 1) gates(s->W2, s->bp[1][lc], hr + 1,  2 * H, lc, acc);
            else             gates(s->W3, s->bp[2][lc], hr + 52, 2 * H, lc, acc);
        } else if (head_lane && t >= 3) {
            int b = l - 102;
            out[(size_t)(b0 + b) * T_TOT + (t - 3)] = head_dot(s, hr, b);
        } else if (xf_lane && t + 1 < T_IN) {
            xr = input[(size_t)(b0 + l - 102) * T_IN + t + 1];
        }
        ull prt[8];
#pragma unroll
        for (int i = 0; i < 8; i++) prt[i] = __shfl_xor_sync(0xffffffffu, acc[i], 1);

        const bool valid = gate_lane &&
            ((L == 0) ? (t <= T_IN - 1)
                      : (L == 1) ? (t >= 1 && t <= T_IN) : (t >= 2));
        float hn[4];
        if (valid) cell4(acc, prt, sel, creg, hn);
        if (valid)
            *(float4 *)&hw[1 + L * H + j][sel * 4] =
                make_float4(hn[0], hn[1], hn[2], hn[3]);
        if (xf_lane && t + 1 < T_IN) hw[0][l - 102] = xr;
        __syncthreads();
    }

    // ---- drain into buffer 0 (current after even NTICK) ----
    // park c-state; fix h2 rows (h2(511) lives in buf1); out(511) -> x
    if (gate_lane)
        *(float4 *)&s->c[L * H + j][sel * 4] =
            make_float4(creg[0], creg[1], creg[2], creg[3]);
    if (tid < H * BB) {
        int r = tid >> 3, b = tid & 7;
        s->hcat[0][52 + r][b] = s->hcat[1][52 + r][b];
    }
    if (tid < BB) {
        float v = head_dot(s, s->hcat[0], tid);   // h3(511) is in buf0
        out[(size_t)(b0 + tid) * T_TOT + (T_IN - 1)] = v;
        s->hcat[0][0][tid] = v;
    }
    __syncthreads();

    // ===== autoregressive future: all lanes, k-thirds in adjacent lanes =====
    const int  m     = tid & 31, w5 = tid >> 5;
    const int  fpr   = w5 * 10 + m / 3;            // pair 0..101
    const int  fq    = m % 3;                      // k-third
    const bool fact  = (m < 30) && (fpr < 102);
    const int  fp    = fact ? fpr : 101;
    const int  fj    = fp >> 1, fsel = fp & 1;
    const int  psrc  = (3 * ((fp ^ 1) - w5 * 10)) & 31;
    float (*h0)[BB] = s->hcat[0];

    for (int fs = 0; fs < T_FUT; fs++) {
#pragma unroll
        for (int lay = 0; lay < 3; lay++) {
            const float2(*W)[102];
            const float(*V)[BB];
            int k0, k1;
            if (lay == 0)      { W = s->W1; V = h0;      k0 = (fq == 0) ? 0 : (fq == 1) ? 18 : 35;
                                                          k1 = (fq == 0) ? 18 : (fq == 1) ? 35 : 52; }
            else if (lay == 1) { W = s->W2; V = h0 + 1;  k0 = fq * 34; k1 = k0 + 34; }
            else               { W = s->W3; V = h0 + 52; k0 = fq * 34; k1 = k0 + 34; }
            ull acc[8] = {};
            if (fact) {
                if (fq == 0) {
                    float2 bv = s->bp[lay][fp];
                    ull bx = pack2(bv.x), by = pack2(bv.y);
#pragma unroll
                    for (int i = 0; i < 4; i++) { acc[i] = bx; acc[4 + i] = by; }
                }
#pragma unroll 2
                for (int k = k0; k < k1; k++) mac8(acc, W[k][fp], &V[k][0]);
            }
            // reduce the 3 k-thirds (adjacent lanes) then fetch partner pair
            ull prt[8];
#pragma unroll
            for (int i = 0; i < 8; i++) {
                ull t1 = __shfl_down_sync(0xffffffffu, acc[i], 1);
                ull t2 = __shfl_down_sync(0xffffffffu, acc[i], 2);
                acc[i] = add2(add2(acc[i], t1), t2);
            }
#pragma unroll
            for (int i = 0; i < 8; i++)
                prt[i] = __shfl_sync(0xffffffffu, acc[i], psrc);
            __syncthreads();   // all gate reads done before h writes
            if (fact && fq == 0) {
                float4 cv = *(float4 *)&s->c[lay * H + fj][fsel * 4];
                float cr[4] = {cv.x, cv.y, cv.z, cv.w};
                float hn[4];
                cell4(acc, prt, fsel, cr, hn);
                *(float4 *)&s->c[lay * H + fj][fsel * 4] =
                    make_float4(cr[0], cr[1], cr[2], cr[3]);
                *(float4 *)&h0[1 + lay * H + fj][fsel * 4] =
                    make_float4(hn[0], hn[1], hn[2], hn[3]);
            }
            __syncthreads();
        }
        if (tid < BB) {
            float v = head_dot(s, h0, tid);
            out[(size_t)(b0 + tid) * T_TOT + T_IN + fs] = v;
            h0[0][tid] = v;
        }
        __syncthreads();
    }
}

extern "C" void kernel_launch(void *const *d_in, const int *in_sizes, int n_in,
                              void *d_out, int out_size) {
    (void)in_sizes; (void)n_in; (void)out_size;
    cudaFuncSetAttribute(lstm_seq_kernel,
                         cudaFuncAttributeMaxDynamicSharedMemorySize,
                         (int)sizeof(Smem));
    lstm_seq_kernel<<<NCTA, TPB, sizeof(Smem)>>>(
        (const float *)d_in[0],
        (const float *)d_in[1], (const float *)d_in[2],
        (const float *)d_in[3], (const float *)d_in[4],
        (const float *)d_in[5], (const float *)d_in[6],
        (const float *)d_in[7], (const float *)d_in[8],
        (const float *)d_in[9], (const float *)d_in[10],
        (const float *)d_in[11], (const float *)d_in[12],
        (const float *)d_in[13], (const float *)d_in[14],
        (float *)d_out);
}